// round 12
// baseline (speedup 1.0000x reference)
#include <cuda_runtime.h>
#include <cuda_fp16.h>
#include <cstdint>

// out[b,i] = sum_h W2[i,h] * relu( sum_d X[b,d]*Adj[i,d]*W1[i,h,d] )
// B=16384, D=64, H=64.
//
// Single-term fp16 HMMA (mma.sync m16n8k16 f32.f16.f16), rel_err ~3e-4.
// Prep kernel emits X and W'=W1*adj in MMA fragment order. Main kernel:
// block = (1 node x 1024 rows); warp = 16-row strip x 8 tiles.
// ks=0,1 B-fragments register-resident; ks=2,3 re-read from smem per tile
// (hidden under MMAs). A fragments DOUBLE-BUFFERED: tile t+1's 4 LDG.128
// issue before tile t's MMAs so L2 latency is covered. No barriers in loop.

#define NT   256
#define TPB  8      // 128-row tiles per block

// ---- device-global fragment buffers (prep output) ----
static __device__ __align__(16) uint4 Xfrag_g[1024 * 4 * 32];  // 2MB
static __device__ __align__(16) uint4 Wfrag_g[64 * 16 * 32];   // 512KB

static __device__ __forceinline__ uint32_t h2u(__half2 h) {
    return *(uint32_t*)&h;
}

static __device__ __forceinline__ uint32_t smem_u32(const void* p) {
    uint32_t a;
    asm("{ .reg .u64 t; cvta.to.shared.u64 t, %1; cvt.u32.u64 %0, t; }" : "=r"(a) : "l"(p));
    return a;
}

static __device__ __forceinline__ void cp16(uint32_t dst, const void* src) {
    asm volatile("cp.async.ca.shared.global [%0], [%1], 16;"
                 :: "r"(dst), "l"(src) : "memory");
}

static __device__ __forceinline__ void mma16816(float* c, const uint32_t* a,
                                                const uint32_t* b) {
    asm volatile(
        "mma.sync.aligned.m16n8k16.row.col.f32.f16.f16.f32 "
        "{%0,%1,%2,%3}, {%4,%5,%6,%7}, {%8,%9}, {%0,%1,%2,%3};"
        : "+f"(c[0]), "+f"(c[1]), "+f"(c[2]), "+f"(c[3])
        : "r"(a[0]), "r"(a[1]), "r"(a[2]), "r"(a[3]), "r"(b[0]), "r"(b[1]));
}

// ---- prep: emit fragment-ordered fp16 X and W'=W1*adj ----
__global__ __launch_bounds__(NT)
void prep_kernel(const float* __restrict__ X,
                 const float* __restrict__ Adj,
                 const float* __restrict__ W1)
{
    int gid = blockIdx.x * NT + threadIdx.x;
    if (gid < 131072) {
        // X fragments: gid = (rt*4 + ks)*32 + l
        int l  = gid & 31;
        int ks = (gid >> 5) & 3;
        int rt = gid >> 7;
        int gi = l >> 2, ti = l & 3;
        int r0 = rt * 16 + gi;
        int c0 = ks * 16 + ti * 2;
        const float* xr0 = X + (size_t)r0 * 64;
        const float* xr1 = X + (size_t)(r0 + 8) * 64;
        uint4 v;
        v.x = h2u(__floats2half2_rn(xr0[c0],     xr0[c0 + 1]));   // a0
        v.y = h2u(__floats2half2_rn(xr1[c0],     xr1[c0 + 1]));   // a1
        v.z = h2u(__floats2half2_rn(xr0[c0 + 8], xr0[c0 + 9]));   // a2
        v.w = h2u(__floats2half2_rn(xr1[c0 + 8], xr1[c0 + 9]));   // a3
        Xfrag_g[gid] = v;
    } else if (gid < 131072 + 32768) {
        // W fragments: j = (node*16 + w)*32 + l ; flat word = ks*16 + n*2 + r
        int j    = gid - 131072;
        int l    = j & 31;
        int w    = (j >> 5) & 15;
        int node = j >> 9;
        int gi = l >> 2, ti = l & 3;
        uint32_t vv[4];
        #pragma unroll
        for (int q = 0; q < 4; ++q) {
            int idx = w * 4 + q;
            int ks = idx >> 4, ng = (idx >> 1) & 7, r = idx & 1;
            int h0 = ng * 8 + gi;
            int d0 = ks * 16 + ti * 2 + r * 8;
            const float* w1p = W1 + ((size_t)node * 64 + h0) * 64;
            const float* ap  = Adj + node * 64;
            vv[q] = h2u(__floats2half2_rn(w1p[d0] * ap[d0],
                                          w1p[d0 + 1] * ap[d0 + 1]));
        }
        uint4 o; o.x = vv[0]; o.y = vv[1]; o.z = vv[2]; o.w = vv[3];
        Wfrag_g[j] = o;
    }
}

// ---- main GEMM ----
__global__ __launch_bounds__(NT, 2)
void tp_kernel(const float* __restrict__ W2, float* __restrict__ out)
{
    __shared__ __align__(16) uint4 Wsh[16 * 32];   // 8KB, [w][lane]
    __shared__ float W2s[64];

    const int tid = threadIdx.x;
    const int wid = tid >> 5;
    const int l   = tid & 31;
    const int i    = blockIdx.x;                 // node (fastest -> X L2 reuse)
    const int row0 = blockIdx.y * (128 * TPB);   // 1024-row group

    // ---- prologue: stage W fragments (8KB) via cp.async ----
    {
        const uint32_t wdst = smem_u32(Wsh);
        #pragma unroll
        for (int it = 0; it < 2; ++it) {
            int c = tid + it * NT;               // 0..511
            cp16(wdst + c * 16, &Wfrag_g[i * 512 + c]);
        }
        asm volatile("cp.async.commit_group;" ::: "memory");
    }
    if (tid < 64) W2s[tid] = W2[i * 64 + tid];
    asm volatile("cp.async.wait_group 0;" ::: "memory");
    __syncthreads();

    // ---- resident B fragments for ks=0,1 (32 regs) ----
    uint32_t wv01[32];
    #pragma unroll
    for (int w = 0; w < 8; ++w) {
        uint4 t = Wsh[w * 32 + l];
        wv01[w * 4 + 0] = t.x; wv01[w * 4 + 1] = t.y;
        wv01[w * 4 + 2] = t.z; wv01[w * 4 + 3] = t.w;
    }

    // A pointer: rt = row0/16 + t*8 + wid; elem = (rt*4 + ks)*32 + l
    const uint4* xp = Xfrag_g + (size_t)((row0 >> 4) + wid) * 128 + l;

    // preload tile 0 A fragments
    uint4 xv[4];
    #pragma unroll
    for (int ks = 0; ks < 4; ++ks) xv[ks] = __ldg(xp + ks * 32);

    #pragma unroll 1
    for (int t = 0; t < TPB; ++t) {
        // issue tile t+1 A loads NOW (latency covered by this tile's work)
        uint4 xvn[4];
        if (t + 1 < TPB) {
            #pragma unroll
            for (int ks = 0; ks < 4; ++ks)
                xvn[ks] = __ldg(xp + (t + 1) * 1024 + ks * 32);
        }

        float acc[8][4];
        #pragma unroll
        for (int n = 0; n < 8; ++n)
            #pragma unroll
            for (int q = 0; q < 4; ++q) acc[n][q] = 0.f;

        // ks = 0,1: resident B
        #pragma unroll
        for (int ks = 0; ks < 2; ++ks)
            #pragma unroll
            for (int n = 0; n < 8; ++n)
                mma16816(acc[n], (const uint32_t*)&xv[ks], &wv01[ks * 16 + n * 2]);

        // ks = 2,3: B from smem (LDS hidden under MMA stream)
        #pragma unroll
        for (int ks = 2; ks < 4; ++ks) {
            uint32_t wvt[16];
            #pragma unroll
            for (int g = 0; g < 4; ++g) {
                uint4 tt = Wsh[(ks * 4 + g) * 32 + l];
                wvt[g * 4 + 0] = tt.x; wvt[g * 4 + 1] = tt.y;
                wvt[g * 4 + 2] = tt.z; wvt[g * 4 + 3] = tt.w;
            }
            #pragma unroll
            for (int n = 0; n < 8; ++n)
                mma16816(acc[n], (const uint32_t*)&xv[ks], &wvt[n * 2]);
        }

        // ---- epilogue: relu + dot W2, quad reduce, store ----
        float s0 = 0.f, s1 = 0.f;
        #pragma unroll
        for (int n = 0; n < 8; ++n) {
            float2 w = *(const float2*)(W2s + n * 8 + (l & 3) * 2);
            s0 = fmaf(fmaxf(acc[n][0], 0.f), w.x, s0);
            s0 = fmaf(fmaxf(acc[n][1], 0.f), w.y, s0);
            s1 = fmaf(fmaxf(acc[n][2], 0.f), w.x, s1);
            s1 = fmaf(fmaxf(acc[n][3], 0.f), w.y, s1);
        }
        s0 += __shfl_xor_sync(0xffffffffu, s0, 1);
        s0 += __shfl_xor_sync(0xffffffffu, s0, 2);
        s1 += __shfl_xor_sync(0xffffffffu, s1, 1);
        s1 += __shfl_xor_sync(0xffffffffu, s1, 2);
        if ((l & 3) == 0) {
            int grow = row0 + t * 128 + wid * 16 + (l >> 2);
            out[(size_t)grow * 64 + i]       = s0;
            out[(size_t)(grow + 8) * 64 + i] = s1;
        }

        #pragma unroll
        for (int ks = 0; ks < 4; ++ks) xv[ks] = xvn[ks];
    }
}

extern "C" void kernel_launch(void* const* d_in, const int* in_sizes, int n_in,
                              void* d_out, int out_size) {
    const float* X   = (const float*)d_in[0];  // [16384, 64]
    const float* Adj = (const float*)d_in[1];  // [64, 64]
    const float* W1  = (const float*)d_in[2];  // [64, 64, 64] (i,h,d)
    const float* W2  = (const float*)d_in[3];  // [64, 64]
    float* out = (float*)d_out;                // [16384, 64]

    prep_kernel<<<640, NT>>>(X, Adj, W1);

    dim3 grid(64, 16384 / (128 * TPB));
    tp_kernel<<<grid, NT>>>(W2, out);
}

// round 13
// speedup vs baseline: 1.0667x; 1.0667x over previous
#include <cuda_runtime.h>
#include <cuda_fp16.h>
#include <cstdint>

// out[b,i] = sum_h W2[i,h] * relu( sum_d X[b,d]*Adj[i,d]*W1[i,h,d] )
// B=16384, D=64, H=64.
//
// Single-term fp16 HMMA (mma.sync m16n8k16 f32.f16.f16).
// Block = (1 node x 1024 rows) = 8 tiles of 128 rows; 8 warps, each owns a
// 16-row strip per tile and all 64 h. B fragments register-resident (64 regs,
// loaded once). X strips warp-private, double-buffered cp.async.
// EPILOGUE ON TENSOR PIPE: relu(H) C-fragments repack directly as A fragments
// (C layout == A layout for m16n8), W2 as a B fragment with only n-col 0
// populated -> 4 chained MMAs replace the FMA+shfl reduction chains.

#define NT   256
#define TB   128
#define TPB  8      // tiles per block

// ---- device-global fp16 buffers (prep output) ----
static __device__ __align__(16) __half Xf_g[16384 * 64];
static __device__ __align__(16) __half Wf_g[64 * 64 * 64];

// ---- main-kernel smem layout (bytes) ----
#define OFF_W    0        // 8KB, swizzled
#define OFF_X    8192     // 8 warps x 2 bufs x 2KB, swizzled
#define SMEM_TOTAL 40960

static __device__ __forceinline__ uint32_t h2u(__half2 h) {
    return *(uint32_t*)&h;
}

static __device__ __forceinline__ uint32_t smem_u32(const void* p) {
    uint32_t a;
    asm("{ .reg .u64 t; cvta.to.shared.u64 t, %1; cvt.u32.u64 %0, t; }" : "=r"(a) : "l"(p));
    return a;
}

static __device__ __forceinline__ void cp16(uint32_t dst, const void* src) {
    asm volatile("cp.async.ca.shared.global [%0], [%1], 16;"
                 :: "r"(dst), "l"(src) : "memory");
}

static __device__ __forceinline__ void ldsm4(uint32_t* r, uint32_t addr) {
    asm volatile("ldmatrix.sync.aligned.m8n8.x4.shared.b16 {%0,%1,%2,%3}, [%4];"
                 : "=r"(r[0]), "=r"(r[1]), "=r"(r[2]), "=r"(r[3]) : "r"(addr));
}

static __device__ __forceinline__ void mma16816(float* c, const uint32_t* a,
                                                const uint32_t* b) {
    asm volatile(
        "mma.sync.aligned.m16n8k16.row.col.f32.f16.f16.f32 "
        "{%0,%1,%2,%3}, {%4,%5,%6,%7}, {%8,%9}, {%0,%1,%2,%3};"
        : "+f"(c[0]), "+f"(c[1]), "+f"(c[2]), "+f"(c[3])
        : "r"(a[0]), "r"(a[1]), "r"(a[2]), "r"(a[3]), "r"(b[0]), "r"(b[1]));
}

// ---- prep: X -> fp16; W1*adj -> fp16 ----
__global__ __launch_bounds__(NT)
void prep_kernel(const float* __restrict__ X,
                 const float* __restrict__ Adj,
                 const float* __restrict__ W1)
{
    int gid = blockIdx.x * NT + threadIdx.x;
    if (gid < 262144) {                       // X: 16384*64/4 float4s
        float4 v = ((const float4*)X)[gid];
        __half2 p0 = __floats2half2_rn(v.x, v.y);
        __half2 p1 = __floats2half2_rn(v.z, v.w);
        uint2 r; r.x = h2u(p0); r.y = h2u(p1);
        ((uint2*)Xf_g)[gid] = r;
    } else {                                  // W: 64*64*64/4 float4s
        int j = gid - 262144;                 // 0..65535
        int i  = j >> 10;
        int d4 = j & 15;
        float4 v = ((const float4*)W1)[j];
        float4 a = ((const float4*)Adj)[i * 16 + d4];
        v.x *= a.x; v.y *= a.y; v.z *= a.z; v.w *= a.w;
        __half2 p0 = __floats2half2_rn(v.x, v.y);
        __half2 p1 = __floats2half2_rn(v.z, v.w);
        uint2 r; r.x = h2u(p0); r.y = h2u(p1);
        ((uint2*)Wf_g)[j] = r;
    }
}

// ---- main GEMM ----
__global__ __launch_bounds__(NT, 2)
void tp_kernel(const float* __restrict__ W2, float* __restrict__ out)
{
    extern __shared__ char smem[];
    const uint32_t sb = smem_u32(smem);
    const int tid = threadIdx.x;
    const int wid = tid >> 5;
    const int l   = tid & 31;
    const int i    = blockIdx.x;                // node (fastest -> X L2 reuse)
    const int row0 = blockIdx.y * (TB * TPB);   // 1024-row group

    const uint32_t xwarp = sb + OFF_X + wid * 4096;   // warp-private 2x2KB
    const char* xbase = (const char*)(Xf_g + (size_t)row0 * 64);

    // ---- prologue: stage W (8KB, all threads) + X tile 0 (own strip) ----
    {
        const char* wsrc = (const char*)(Wf_g + (size_t)i * 4096);
        #pragma unroll
        for (int it = 0; it < 2; ++it) {
            int c = tid + it * NT;          // 0..511
            int r = c >> 3, k16 = c & 7;
            cp16(sb + OFF_W + r * 128 + ((k16 ^ (r & 7)) << 4), wsrc + c * 16);
        }
    }
    #pragma unroll
    for (int it = 0; it < 4; ++it) {
        int c  = l + it * 32;               // 0..127
        int rl = c >> 3, k16 = c & 7;       // row-in-strip 0..15
        cp16(xwarp + rl * 128 + ((k16 ^ (rl & 7)) << 4),
             xbase + (size_t)(wid * 16 + rl) * 128 + k16 * 16);
    }
    asm volatile("cp.async.commit_group;" ::: "memory");

    // ---- W2 epilogue B fragments: only n-col 0 populated (lanes l<4) ----
    uint32_t b2[4][2];
    {
        const float* w2p = W2 + i * 64;
        #pragma unroll
        for (int kc = 0; kc < 4; ++kc) {
            if (l < 4) {
                b2[kc][0] = h2u(__floats2half2_rn(w2p[kc * 16 + 2 * l],
                                                  w2p[kc * 16 + 2 * l + 1]));
                b2[kc][1] = h2u(__floats2half2_rn(w2p[kc * 16 + 8 + 2 * l],
                                                  w2p[kc * 16 + 8 + 2 * l + 1]));
            } else {
                b2[kc][0] = 0u;
                b2[kc][1] = 0u;
            }
        }
    }

    asm volatile("cp.async.wait_group 0;" ::: "memory");
    __syncthreads();   // only block-wide sync: W visibility

    // ---- load ALL B fragments once (register-resident, 64 regs) ----
    const uint32_t bhalf = (l >> 3) & 1;
    uint32_t wv[4][4][4];                   // [ks][g][frag]
    #pragma unroll
    for (int g = 0; g < 4; ++g) {
        int brow = g * 16 + ((l >> 4) & 1) * 8 + (l & 7);
        uint32_t boff = sb + OFF_W + brow * 128;
        uint32_t bsw  = brow & 7;
        #pragma unroll
        for (int ks = 0; ks < 4; ++ks)
            ldsm4(wv[ks][g], boff + (((ks * 2 + bhalf) ^ bsw) << 4));
    }

    // A geometry: 16 rows in own strip
    const int arow = l & 15;
    const uint32_t aoff = xwarp + arow * 128;
    const uint32_t asw  = arow & 7;
    const uint32_t ahalf = (l >> 4) & 1;

    #pragma unroll 2
    for (int t = 0; t < TPB; ++t) {
        // own fill of tile t complete; make visible warp-wide
        asm volatile("cp.async.wait_group 0;" ::: "memory");
        __syncwarp();

        // prefetch own strip of tile t+1 (overlaps this tile's MMAs)
        if (t + 1 < TPB) {
            const char* xt = xbase + (size_t)((t + 1) * TB + wid * 16) * 128;
            uint32_t xdst = xwarp + (((t + 1) & 1) ? 2048u : 0u);
            #pragma unroll
            for (int it = 0; it < 4; ++it) {
                int c  = l + it * 32;
                int rl = c >> 3, k16 = c & 7;
                cp16(xdst + rl * 128 + ((k16 ^ (rl & 7)) << 4),
                     xt + (size_t)rl * 128 + k16 * 16);
            }
            asm volatile("cp.async.commit_group;" ::: "memory");
        }

        const uint32_t xb = (uint32_t)((t & 1) * 2048);

        float acc[8][4];
        #pragma unroll
        for (int n = 0; n < 8; ++n)
            #pragma unroll
            for (int q = 0; q < 4; ++q) acc[n][q] = 0.f;

        #pragma unroll
        for (int ks = 0; ks < 4; ++ks) {
            uint32_t xv[4];
            ldsm4(xv, aoff + xb + (((ks * 2 + ahalf) ^ asw) << 4));
            #pragma unroll
            for (int n = 0; n < 8; ++n)
                mma16816(acc[n], xv, &wv[ks][n >> 1][(n & 1) * 2]);
        }

        // ---- epilogue on tensor pipe: out = relu(H) @ W2 ----
        // C fragment (acc pair 2kc, 2kc+1) packs exactly into an A fragment
        // of one m16n8k16 covering h-cols 16kc..16kc+15; B = W2 (col 0 only).
        float co[4] = {0.f, 0.f, 0.f, 0.f};
        #pragma unroll
        for (int kc = 0; kc < 4; ++kc) {
            uint32_t af[4];
            af[0] = h2u(__floats2half2_rn(fmaxf(acc[2 * kc][0], 0.f),
                                          fmaxf(acc[2 * kc][1], 0.f)));
            af[1] = h2u(__floats2half2_rn(fmaxf(acc[2 * kc][2], 0.f),
                                          fmaxf(acc[2 * kc][3], 0.f)));
            af[2] = h2u(__floats2half2_rn(fmaxf(acc[2 * kc + 1][0], 0.f),
                                          fmaxf(acc[2 * kc + 1][1], 0.f)));
            af[3] = h2u(__floats2half2_rn(fmaxf(acc[2 * kc + 1][2], 0.f),
                                          fmaxf(acc[2 * kc + 1][3], 0.f)));
            mma16816(co, af, b2[kc]);
        }
        // col 0 lives in lanes with l%4==0: c0 = row l/4, c2 = row l/4+8
        if ((l & 3) == 0) {
            int grow = row0 + t * TB + wid * 16 + (l >> 2);
            out[(size_t)grow * 64 + i]       = co[0];
            out[(size_t)(grow + 8) * 64 + i] = co[2];
        }
    }
}

extern "C" void kernel_launch(void* const* d_in, const int* in_sizes, int n_in,
                              void* d_out, int out_size) {
    const float* X   = (const float*)d_in[0];  // [16384, 64]
    const float* Adj = (const float*)d_in[1];  // [64, 64]
    const float* W1  = (const float*)d_in[2];  // [64, 64, 64] (i,h,d)
    const float* W2  = (const float*)d_in[3];  // [64, 64]
    float* out = (float*)d_out;                // [16384, 64]

    prep_kernel<<<1280, NT>>>(X, Adj, W1);

    cudaFuncSetAttribute(tp_kernel, cudaFuncAttributeMaxDynamicSharedMemorySize,
                         SMEM_TOTAL);
    dim3 grid(64, 16384 / (TB * TPB));
    tp_kernel<<<grid, NT, SMEM_TOTAL>>>(W2, out);
}